// round 6
// baseline (speedup 1.0000x reference)
#include <cuda_runtime.h>
#include <cstdint>

// Problem: states [B=64, L=4096, D=256] f32; w [256] f32; bias scalar f32.
// out[b,l] = reverse_cumsum_l( dot(states[b,l,:], w) + bias )
//
// Two kernels linked by PDL (programmatic dependent launch):
//  1) dot_kernel: 1 warp per (b,l) row, __ldcs streaming loads (evict-first).
//     Proven at ~38.6us (= 6.66 TB/s, ~83% of HBM spec).
//  2) rcumsum_kernel: launched with programmatic stream serialization so its
//     launch overhead overlaps the primary's tail; blocks wait in
//     cudaGridDependencySynchronize() (implicit completion trigger => full
//     visibility of the primary's stores, no fences/atomics needed).

static constexpr int B = 64;
static constexpr int L = 4096;
static constexpr int D = 256;          // 64 float4 per row
static constexpr int ROWS = B * L;     // 262144

__global__ void __launch_bounds__(256)
dot_kernel(const float4* __restrict__ states4,
           const float4* __restrict__ w4,
           const float*  __restrict__ bias,
           float* __restrict__ out)
{
    int gwarp = (blockIdx.x * blockDim.x + threadIdx.x) >> 5;
    int lane  = threadIdx.x & 31;

    const float4* row = states4 + (size_t)gwarp * (D / 4);

    // streaming loads, evict-first: states are touched exactly once
    float4 a0 = __ldcs(&row[lane]);
    float4 a1 = __ldcs(&row[lane + 32]);
    float4 w0 = __ldg(&w4[lane]);
    float4 w1 = __ldg(&w4[lane + 32]);

    float s = a0.x * w0.x + a0.y * w0.y + a0.z * w0.z + a0.w * w0.w
            + a1.x * w1.x + a1.y * w1.y + a1.z * w1.z + a1.w * w1.w;

    #pragma unroll
    for (int off = 16; off > 0; off >>= 1)
        s += __shfl_xor_sync(0xFFFFFFFFu, s, off);

    if (lane == 0)
        out[gwarp] = s + __ldg(bias);
}

// In-place reverse cumulative sum along L for each batch row.
// grid = B blocks, 1024 threads, each thread owns one float4.
// Waits on the primary grid via PDL before touching data.
__global__ void __launch_bounds__(1024)
rcumsum_kernel(float* __restrict__ data)
{
    const int b    = blockIdx.x;
    const int t    = threadIdx.x;
    const int lane = t & 31;
    const int wid  = t >> 5;
    float4* p = reinterpret_cast<float4*>(data + (size_t)b * L) + t;

    // Block until the dot kernel has fully completed (implicit trigger at
    // primary completion => all its stores are visible).
    cudaGridDependencySynchronize();

    float4 x = *p;
    float v0 = x.x, v1 = x.y, v2 = x.z, v3 = x.w;
    float total = v0 + v1 + v2 + v3;

    // inclusive SUFFIX scan within warp: lane i -> sum over lanes >= i
    float s = total;
    #pragma unroll
    for (int off = 1; off < 32; off <<= 1) {
        float n = __shfl_down_sync(0xFFFFFFFFu, s, off);
        if (lane < 32 - off) s += n;
    }

    __shared__ float warp_off[32];
    {
        __shared__ float warp_tot[32];
        if (lane == 0) warp_tot[wid] = s;   // lane 0's s == warp full sum
        __syncthreads();

        if (wid == 0) {
            float ws = warp_tot[lane];
            float ss = ws;
            #pragma unroll
            for (int off = 1; off < 32; off <<= 1) {
                float n = __shfl_down_sync(0xFFFFFFFFu, ss, off);
                if (lane < 32 - off) ss += n;
            }
            warp_off[lane] = ss - ws;       // exclusive suffix of warp sums
        }
        __syncthreads();
    }

    // exclusive suffix for this thread: warps after mine + lanes after me
    float offset = warp_off[wid] + (s - total);

    float q3 = offset + v3;
    float q2 = q3 + v2;
    float q1 = q2 + v1;
    float q0 = q1 + v0;

    *p = make_float4(q0, q1, q2, q3);
}

extern "C" void kernel_launch(void* const* d_in, const int* in_sizes, int n_in,
                              void* d_out, int out_size)
{
    const float4* states4 = (const float4*)d_in[0];
    const float4* w4      = (const float4*)d_in[1];
    const float*  bias    = (const float*)d_in[2];
    float* out = (float*)d_out;

    dot_kernel<<<ROWS / 8, 256>>>(states4, w4, bias, out);

    // PDL launch of the scan: overlap its launch/scheduling with the
    // primary's tail; dependency enforced by cudaGridDependencySynchronize.
    cudaLaunchConfig_t cfg = {};
    cfg.gridDim  = dim3(B, 1, 1);
    cfg.blockDim = dim3(1024, 1, 1);
    cfg.dynamicSmemBytes = 0;
    cfg.stream = 0;
    cudaLaunchAttribute attr[1];
    attr[0].id = cudaLaunchAttributeProgrammaticStreamSerialization;
    attr[0].val.programmaticStreamSerializationAllowed = 1;
    cfg.attrs = attr;
    cfg.numAttrs = 1;
    cudaLaunchKernelEx(&cfg, rcumsum_kernel, out);
}